// round 1
// baseline (speedup 1.0000x reference)
#include <cuda_runtime.h>
#include <stdint.h>

#define NALGOS 64
#define NTASKS 1024
#define LXN    512
#define LOG2E_F 1.4426950408889634f

// Scratch (no allocations allowed): G = TM[lx[s], lx[t]] and per-step drive u[a][s]
__device__ float g_G[LXN * LXN];
__device__ float g_u[NALGOS * LXN];

// ---------------------------------------------------------------------------
// (2^w - 1)/(2^w + 1)  ==  2*sigmoid(z) - 1  for  w = z * log2(e).
// Entirely FMA/ALU: no MUFU (MUFU would bottleneck the whole kernel at ~74/cyc).
// ---------------------------------------------------------------------------
__device__ __forceinline__ float sig2m1_w(float w) {
    w = fminf(fmaxf(w, -50.0f), 50.0f);
    // round-to-nearest via magic add (intrinsics prevent reassociation folding)
    float ws = __fadd_rn(w, 12582912.0f);          // 1.5 * 2^23
    int   e  = (int)((unsigned)__float_as_int(ws) << 23);   // n << 23 exactly
    float f  = __fadd_rn(w, -__fadd_rn(ws, -12582912.0f));  // f in [-0.5, 0.5]
    // 2^f, degree-5 Taylor (trunc err ~2.4e-6 at |f|=0.5)
    float p = 1.3333558146e-3f;
    p = fmaf(p, f, 9.6181291076e-3f);
    p = fmaf(p, f, 5.5504108664e-2f);
    p = fmaf(p, f, 2.4022650696e-1f);
    p = fmaf(p, f, 6.9314718056e-1f);
    p = fmaf(p, f, 1.0f);
    float y = __int_as_float(__float_as_int(p) + e);        // 2^w
    float b = y + 1.0f;
    // reciprocal: bit-trick seed + 3 Newton steps (rel err ~4e-9), no MUFU
    float rb = __int_as_float(0x7EF311C3 - __float_as_int(b));
    rb = rb * fmaf(-b, rb, 2.0f);
    rb = rb * fmaf(-b, rb, 2.0f);
    rb = rb * fmaf(-b, rb, 2.0f);
    return fmaf(-2.0f, rb, 1.0f);                           // 1 - 2/(y+1)
}

// ---------------------------------------------------------------------------
// Kernel 0: G[s][t] = TM[lx[s]][lx[t]]  (coalesced layout for phase 1)
// ---------------------------------------------------------------------------
__global__ void build_G(const int* __restrict__ lx, const float* __restrict__ TM) {
    int s = blockIdx.x;
    int t = threadIdx.x;
    int row = __ldg(lx + s);
    int col = __ldg(lx + t);
    g_G[s * LXN + t] = __ldg(TM + row * NTASKS + col);
}

// ---------------------------------------------------------------------------
// Phase 1: the serial chain. One warp per algo. Lane l tracks columns
// lx[l + 32*i], i=0..15. Step s's "due" sig lives on lane s%32, slot s/32.
// Template chunk index keeps r[C]/c1[C] as static register indices.
// ---------------------------------------------------------------------------
template <int C>
__device__ __forceinline__ void p1_chunk(float (&r)[16], const float (&c1)[16],
                                         float (&gb)[4][16], float& u_val,
                                         float* uout, int lane,
                                         float mem, float eff, float boost) {
#pragma unroll 4
    for (int k = 0; k < 32; ++k) {
        int s = C * 32 + k;
        float u = __shfl_sync(0xffffffffu, u_val, k);       // broadcast u[s]
        if (lane == 0) uout[s] = u;
        int q = k & 3;                                      // static under unroll-4
#pragma unroll
        for (int i = 0; i < 16; ++i)
            r[i] = fmaf(r[i], mem, gb[q][i] * u);
        // refill pipeline slot with step s+4 (depth-4 covers ~L2 latency)
        if (s + 4 < LXN) {
            const float* gp = g_G + (s + 4) * LXN + lane;
#pragma unroll
            for (int i = 0; i < 16; ++i)
                gb[q][i] = __ldg(gp + 32 * i);
        }
        // produce p[s+1] / u[s+1] on its owner lane
        if (k < 31) {
            if (lane == k + 1) {
                float p = sig2m1_w(r[C] * c1[C]);
                u_val = fmaf(p, boost, eff);
            }
        } else if constexpr (C < 15) {
            if (lane == 0) {
                float p = sig2m1_w(r[C + 1] * c1[C + 1]);
                u_val = fmaf(p, boost, eff);
            }
        }
    }
}

template <int C>
__device__ __forceinline__ void p1_run(float (&r)[16], const float (&c1)[16],
                                       float (&gb)[4][16], float& u_val,
                                       float* uout, int lane,
                                       float mem, float eff, float boost) {
    if constexpr (C < 16) {
        p1_chunk<C>(r, c1, gb, u_val, uout, lane, mem, eff, boost);
        p1_run<C + 1>(r, c1, gb, u_val, uout, lane, mem, eff, boost);
    }
}

__global__ void __launch_bounds__(32, 1) phase1(
    const int* __restrict__ lx, const float* __restrict__ diff,
    const float* __restrict__ eff_, const float* __restrict__ mem_,
    const float* __restrict__ boost_) {
    int a = blockIdx.x;
    int lane = threadIdx.x;
    float mem = __ldg(mem_ + a), eff = __ldg(eff_ + a), boost = __ldg(boost_ + a);

    float r[16], c1[16];
#pragma unroll
    for (int i = 0; i < 16; ++i) {
        r[i] = 0.0f;
        c1[i] = LOG2E_F / __ldg(diff + __ldg(lx + 32 * i + lane));
    }
    // warm up depth-4 G pipeline (steps 0..3)
    float gb[4][16];
#pragma unroll
    for (int q = 0; q < 4; ++q) {
        const float* gp = g_G + q * LXN + lane;
#pragma unroll
        for (int i = 0; i < 16; ++i) gb[q][i] = __ldg(gp + 32 * i);
    }
    float u_val = eff;                 // p[0] = 0  ->  u[0] = eff
    float* uout = g_u + a * LXN;
    p1_run<0>(r, c1, gb, u_val, uout, lane, mem, eff, boost);
}

// ---------------------------------------------------------------------------
// Phase 2: 65536 independent column scans. Shared-memory 32x32 transpose per
// warp so all STG to out[a][j][t] (t innermost, stride 513) are 128B coalesced.
// ---------------------------------------------------------------------------
__global__ void __launch_bounds__(128) phase2(
    const int* __restrict__ lx, const float* __restrict__ TM,
    const float* __restrict__ diff, const float* __restrict__ mem_,
    float* __restrict__ out) {
    int a   = blockIdx.y;
    int tid = threadIdx.x;
    int j   = blockIdx.x * 128 + tid;

    __shared__ float u_sh[LXN];
    __shared__ int   off_sh[LXN];
    __shared__ float tbuf[4][32][33];   // [warp][j-row][t] ; +1 pad: conflict-free

    for (int i = tid; i < LXN; i += 128) {
        u_sh[i]  = g_u[a * LXN + i];
        off_sh[i] = __ldg(lx + i) << 10;   // lx[s] * NTASKS
    }
    __syncthreads();

    float mem = __ldg(mem_ + a);
    float c1  = LOG2E_F / __ldg(diff + j);
    float r   = 0.0f;
    int warp = tid >> 5, lane = tid & 31;

    unsigned obase = (unsigned)(a * NTASKS + j) * 513u;
    out[obase] = 0.0f;                                  // step-0 zeros
    unsigned tbase = (unsigned)(a * NTASKS + blockIdx.x * 128 + warp * 32) * 513u
                     + 1u + (unsigned)lane;

    for (int c = 0; c < 16; ++c) {
#pragma unroll 8
        for (int k = 0; k < 32; ++k) {
            int s = c * 32 + k;
            float val = __ldg(TM + off_sh[s] + j);      // coalesced 128B/warp, L2-hot
            r = fmaf(r, mem, val * u_sh[s]);
            tbuf[warp][lane][k] = sig2m1_w(r * c1);
        }
        __syncwarp();
        unsigned ob = tbase + (unsigned)(c * 32);
#pragma unroll 8
        for (int row = 0; row < 32; ++row)
            out[ob + (unsigned)row * 513u] = tbuf[warp][row][lane];
        __syncwarp();
    }
}

// ---------------------------------------------------------------------------
extern "C" void kernel_launch(void* const* d_in, const int* in_sizes, int n_in,
                              void* d_out, int out_size) {
    const int*   lx    = (const int*)  d_in[0];
    const float* TM    = (const float*)d_in[1];
    const float* diff  = (const float*)d_in[2];
    const float* eff   = (const float*)d_in[3];
    const float* mem   = (const float*)d_in[4];
    const float* boost = (const float*)d_in[5];
    float* out = (float*)d_out;

    build_G<<<LXN, LXN>>>(lx, TM);
    phase1<<<NALGOS, 32>>>(lx, diff, eff, mem, boost);
    phase2<<<dim3(NTASKS / 128, NALGOS), 128>>>(lx, TM, diff, mem, out);
}

// round 2
// speedup vs baseline: 1.1149x; 1.1149x over previous
#include <cuda_runtime.h>
#include <stdint.h>

#define NALGOS 64
#define NTASKS 1024
#define LXN    512
#define LOG2E_F 1.4426950408889634f

// Scratch (no allocations allowed): G = TM[lx[s], lx[t]] and per-step drive u[a][s]
__device__ float g_G[LXN * LXN];
__device__ float g_u[NALGOS * LXN];

// ---------------------------------------------------------------------------
// 2*sigmoid(z) - 1 = 1 - 2/(2^w + 1), w = z*log2(e).  Pure MUFU: EX2 + RCP.
// ex2.approx saturates (w->+inf => 1, w->-inf => -1), so no clamping needed.
// ---------------------------------------------------------------------------
__device__ __forceinline__ float ex2_approx(float w) {
    float y;
    asm("ex2.approx.ftz.f32 %0, %1;" : "=f"(y) : "f"(w));
    return y;
}
__device__ __forceinline__ float rcp_approx(float b) {
    float r;
    asm("rcp.approx.ftz.f32 %0, %1;" : "=f"(r) : "f"(b));
    return r;
}
__device__ __forceinline__ float sig2m1_w(float w) {
    float y  = ex2_approx(w);
    float rb = rcp_approx(y + 1.0f);
    return fmaf(-2.0f, rb, 1.0f);
}

// ---------------------------------------------------------------------------
// Kernel 0: G[s][t] = TM[lx[s]][lx[t]]  (coalesced layout for phase 1)
// ---------------------------------------------------------------------------
__global__ void build_G(const int* __restrict__ lx, const float* __restrict__ TM) {
    int s = blockIdx.x;
    int t = threadIdx.x;
    int row = __ldg(lx + s);
    int col = __ldg(lx + t);
    g_G[s * LXN + t] = __ldg(TM + row * NTASKS + col);
}

// ---------------------------------------------------------------------------
// Phase 1: the serial chain. One warp per algo. Lane l tracks columns
// lx[l + 32*i], i=0..15. Step s's "due" sig lives on lane s%32, slot s/32.
// Template chunk index keeps r[C]/c1[C] as static register indices.
// Serial chain/step: SHFL(26) + FMA(8) + MUL(4) + EX2(16) + ADD(4) + RCP(16)
// + FMA(4) ~= 78 cyc.
// ---------------------------------------------------------------------------
template <int C>
__device__ __forceinline__ void p1_chunk(float (&r)[16], const float (&c1)[16],
                                         float (&gb)[4][16], float& u_val,
                                         float* uout, int lane,
                                         float mem, float ebp, float nb2) {
#pragma unroll 4
    for (int k = 0; k < 32; ++k) {
        int s = C * 32 + k;
        float u = __shfl_sync(0xffffffffu, u_val, k);       // broadcast u[s]
        if (lane == 0) uout[s] = u;
        int q = k & 3;                                      // static under unroll-4
#pragma unroll
        for (int i = 0; i < 16; ++i)
            r[i] = fmaf(r[i], mem, gb[q][i] * u);
        // refill pipeline slot with step s+4 (depth-4 covers ~L2 latency)
        if (s + 4 < LXN) {
            const float* gp = g_G + (s + 4) * LXN + lane;
#pragma unroll
            for (int i = 0; i < 16; ++i)
                gb[q][i] = __ldg(gp + 32 * i);
        }
        // produce u[s+1] on its owner lane:  u = (eff+boost) - 2*boost/(2^w+1)
        if (k < 31) {
            if (lane == k + 1) {
                float y = ex2_approx(r[C] * c1[C]);
                u_val = fmaf(rcp_approx(y + 1.0f), nb2, ebp);
            }
        } else if constexpr (C < 15) {
            if (lane == 0) {
                float y = ex2_approx(r[C + 1] * c1[C + 1]);
                u_val = fmaf(rcp_approx(y + 1.0f), nb2, ebp);
            }
        }
    }
}

template <int C>
__device__ __forceinline__ void p1_run(float (&r)[16], const float (&c1)[16],
                                       float (&gb)[4][16], float& u_val,
                                       float* uout, int lane,
                                       float mem, float ebp, float nb2) {
    if constexpr (C < 16) {
        p1_chunk<C>(r, c1, gb, u_val, uout, lane, mem, ebp, nb2);
        p1_run<C + 1>(r, c1, gb, u_val, uout, lane, mem, ebp, nb2);
    }
}

__global__ void __launch_bounds__(32, 1) phase1(
    const int* __restrict__ lx, const float* __restrict__ diff,
    const float* __restrict__ eff_, const float* __restrict__ mem_,
    const float* __restrict__ boost_) {
    int a = blockIdx.x;
    int lane = threadIdx.x;
    float mem = __ldg(mem_ + a), eff = __ldg(eff_ + a), boost = __ldg(boost_ + a);
    float ebp = eff + boost;          // u = ebp + nb2 * rcp(2^w + 1)
    float nb2 = -2.0f * boost;

    float r[16], c1[16];
#pragma unroll
    for (int i = 0; i < 16; ++i) {
        r[i] = 0.0f;
        c1[i] = LOG2E_F / __ldg(diff + __ldg(lx + 32 * i + lane));
    }
    // warm up depth-4 G pipeline (steps 0..3)
    float gb[4][16];
#pragma unroll
    for (int q = 0; q < 4; ++q) {
        const float* gp = g_G + q * LXN + lane;
#pragma unroll
        for (int i = 0; i < 16; ++i) gb[q][i] = __ldg(gp + 32 * i);
    }
    float u_val = eff;                 // p[0] = 0  ->  u[0] = eff
    float* uout = g_u + a * LXN;
    p1_run<0>(r, c1, gb, u_val, uout, lane, mem, ebp, nb2);
}

// ---------------------------------------------------------------------------
// Phase 2: 65536 independent column scans. Shared-memory 32x32 transpose per
// warp so all STG to out[a][j][t] (t innermost, stride 513) are 128B coalesced.
// Per step/thread: LDG + MUL + FMA + MUL + EX2 + ADD + RCP + FMA + STS ~ 9 inst.
// Bound: MUFU (~2.1M warp-inst / 74 per cyc ~ 16us) vs 134MB DRAM writes (~17us).
// ---------------------------------------------------------------------------
__global__ void __launch_bounds__(128) phase2(
    const int* __restrict__ lx, const float* __restrict__ TM,
    const float* __restrict__ diff, const float* __restrict__ mem_,
    float* __restrict__ out) {
    int a   = blockIdx.y;
    int tid = threadIdx.x;
    int j   = blockIdx.x * 128 + tid;

    __shared__ float u_sh[LXN];
    __shared__ int   off_sh[LXN];
    __shared__ float tbuf[4][32][33];   // [warp][j-row][t] ; +1 pad: conflict-free

    for (int i = tid; i < LXN; i += 128) {
        u_sh[i]  = g_u[a * LXN + i];
        off_sh[i] = __ldg(lx + i) << 10;   // lx[s] * NTASKS
    }
    __syncthreads();

    float mem = __ldg(mem_ + a);
    float c1  = LOG2E_F / __ldg(diff + j);
    float r   = 0.0f;
    int warp = tid >> 5, lane = tid & 31;

    unsigned obase = (unsigned)(a * NTASKS + j) * 513u;
    out[obase] = 0.0f;                                  // step-0 zeros
    unsigned tbase = (unsigned)(a * NTASKS + blockIdx.x * 128 + warp * 32) * 513u
                     + 1u + (unsigned)lane;

    for (int c = 0; c < 16; ++c) {
#pragma unroll 8
        for (int k = 0; k < 32; ++k) {
            int s = c * 32 + k;
            float val = __ldg(TM + off_sh[s] + j);      // coalesced 128B/warp, L2-hot
            r = fmaf(r, mem, val * u_sh[s]);
            tbuf[warp][lane][k] = sig2m1_w(r * c1);
        }
        __syncwarp();
        unsigned ob = tbase + (unsigned)(c * 32);
#pragma unroll 8
        for (int row = 0; row < 32; ++row)
            out[ob + (unsigned)row * 513u] = tbuf[warp][row][lane];
        __syncwarp();
    }
}

// ---------------------------------------------------------------------------
extern "C" void kernel_launch(void* const* d_in, const int* in_sizes, int n_in,
                              void* d_out, int out_size) {
    const int*   lx    = (const int*)  d_in[0];
    const float* TM    = (const float*)d_in[1];
    const float* diff  = (const float*)d_in[2];
    const float* eff   = (const float*)d_in[3];
    const float* mem   = (const float*)d_in[4];
    const float* boost = (const float*)d_in[5];
    float* out = (float*)d_out;

    build_G<<<LXN, LXN>>>(lx, TM);
    phase1<<<NALGOS, 32>>>(lx, diff, eff, mem, boost);
    phase2<<<dim3(NTASKS / 128, NALGOS), 128>>>(lx, TM, diff, mem, out);
}